// round 14
// baseline (speedup 1.0000x reference)
#include <cuda_runtime.h>
#include <cuda_bf16.h>

// Problem constants
#define L_SEQ  2048
#define B_SZ   2
#define E_DIM  256
#define H_CNT  8
#define D_DIM  32
#define SC2    (0.17677669529663687f * 1.4426950408889634f)   // SCALE * log2(e)

// ---------------------------------------------------------------------------
// Device scratch (allocation-free rule)
// Packed rows use PERMUTED word order:
//   p16(w) = 4*(w&3) + (w>>2)          within each 16-word half
//   p32(w) = 4*(w&7) + (w>>3)          within each 32-word V segment
// so fragment loads become single LDS.128 per lane.
// ---------------------------------------------------------------------------
static __device__ float g_q[B_SZ * H_CNT * L_SEQ * D_DIM];                 // fp32 [bh][l][d]
static __device__ __align__(16) unsigned g_xp[3 * 4096 * 256];             // X inputs, rows m=l*2+b
static __device__ __align__(16) unsigned g_wp[4 * 256 * 256];              // W^T, rows n
static __device__ __align__(16) unsigned g_op[4096 * 256];                 // attention out, rows m
static __device__ __align__(16) unsigned g_k32[16 * 2048 * 32];
static __device__ __align__(16) unsigned g_vh32[16 * 32 * 1024];
static __device__ __align__(16) unsigned g_vl32[16 * 32 * 1024];

// ---------------------------------------------------------------------------
// Helpers
// ---------------------------------------------------------------------------
__device__ __forceinline__ int p16i(int w)    { return 4 * (w & 3) + (w >> 2); }
__device__ __forceinline__ int perm128(int w) { return (w & 0x70) | (4 * (w & 3) + ((w >> 2) & 3)); }
__device__ __forceinline__ int p32i(int w)    { return 4 * (w & 7) + (w >> 3); }

__device__ __forceinline__ unsigned pkbf(float lo, float hi) {
    unsigned r; asm("cvt.rn.bf16x2.f32 %0, %1, %2;" : "=r"(r) : "f"(hi), "f"(lo)); return r;
}
__device__ __forceinline__ void split2(float x, float y, unsigned& hw, unsigned& lw) {
    hw = pkbf(x, y);
    float rx = x - __uint_as_float(hw << 16);
    float ry = y - __uint_as_float(hw & 0xFFFF0000u);
    lw = pkbf(rx, ry);
}
__device__ __forceinline__ float ex2(float x) {
    float y; asm("ex2.approx.ftz.f32 %0, %1;" : "=f"(y) : "f"(x)); return y;
}
__device__ __forceinline__ void mma16816(float* c, const unsigned* a, unsigned b0, unsigned b1) {
    asm volatile("mma.sync.aligned.m16n8k16.row.col.f32.bf16.bf16.f32 "
        "{%0,%1,%2,%3}, {%4,%5,%6,%7}, {%8,%9}, {%0,%1,%2,%3};"
        : "+f"(c[0]), "+f"(c[1]), "+f"(c[2]), "+f"(c[3])
        : "r"(a[0]), "r"(a[1]), "r"(a[2]), "r"(a[3]), "r"(b0), "r"(b1));
}
__device__ __forceinline__ unsigned smem_u32(const void* p) {
    unsigned a;
    asm("{ .reg .u64 t; cvta.to.shared.u64 t, %1; cvt.u32.u64 %0, t; }" : "=r"(a) : "l"(p));
    return a;
}
__device__ __forceinline__ void cpa16(unsigned dst, const void* src) {
    asm volatile("{ .reg .u64 g; cvta.to.global.u64 g, %1; "
                 "cp.async.cg.shared.global [%0], [g], 16; }"
                 :: "r"(dst), "l"(src) : "memory");
}
#define CP_COMMIT() asm volatile("cp.async.commit_group;" ::: "memory")
#define CP_WAIT1()  asm volatile("cp.async.wait_group 1;" ::: "memory")
#define CP_WAIT0()  asm volatile("cp.async.wait_group 0;" ::: "memory")

// ---------------------------------------------------------------------------
// Prep: split-pack X inputs (permuted) and W^T matrices (permuted).
// Blocks 0..47: X. Blocks 48..63: W (4 per matrix).
// ---------------------------------------------------------------------------
__global__ __launch_bounds__(256) void prep_kernel(
    const float* __restrict__ Xq, const float* __restrict__ Xk, const float* __restrict__ Xv,
    const float* __restrict__ Wq, const float* __restrict__ Wk,
    const float* __restrict__ Wv, const float* __restrict__ Wp)
{
    const int bi = blockIdx.x;
    const int t  = threadIdx.x;
    if (bi < 48) {
        const int z  = bi >> 4;
        const int rb = (bi & 15) * 256;
        const float* X = (z == 0) ? Xq : (z == 1) ? Xk : Xv;
        unsigned* dst = g_xp + (size_t)z * 4096 * 256;
        #pragma unroll 4
        for (int i = 0; i < 128; i++) {
            int e = t + i * 256;
            int row = rb + (e >> 7), word = e & 127;
            float2 v = *(const float2*)&X[(size_t)row * 256 + word * 2];
            unsigned hw, lw;
            split2(v.x, v.y, hw, lw);
            int pos = perm128(word);
            dst[(size_t)row * 256 + pos]       = hw;
            dst[(size_t)row * 256 + 128 + pos] = lw;
        }
    } else {
        const int idx = bi - 48;
        const int z = idx >> 2, q = idx & 3;
        const float* W = (z == 0) ? Wq : (z == 1) ? Wk : (z == 2) ? Wv : Wp;
        unsigned* dst = g_wp + (size_t)z * 65536;
        for (int kw = q * 32; kw < q * 32 + 32; kw++) {
            float v0 = W[(size_t)(2 * kw) * 256 + t];
            float v1 = W[(size_t)(2 * kw + 1) * 256 + t];
            unsigned hw, lw;
            split2(v0, v1, hw, lw);
            int pos = perm128(kw);
            dst[(size_t)t * 256 + pos]       = hw;
            dst[(size_t)t * 256 + 128 + pos] = lw;
        }
    }
}

// ---------------------------------------------------------------------------
// mma GEMM core: C[64x64] = A[64x256] @ B^T[64x256], split bf16.
// 8 warps: wr = w&3 (rows wr*16..), wc = w>>2 (cols wc*32..).
// SMEM stage: A 64 rows x 48 words (32 data + 16 pad), B same. 3-stage ring.
// All fragment loads are LDS.128 (permuted layout); stride 48 => octet
// lanes cover disjoint bank halves (conflict-free).
// ---------------------------------------------------------------------------
#define GB_OFF   3072
#define GSTAGE_W 6144
#define GEMM_SMEM (3 * GSTAGE_W * 4)   // 73728 B

__device__ __forceinline__ void mma_gemm_core(
    const unsigned* __restrict__ Ap, const unsigned* __restrict__ Bp,
    int m0, int n0, unsigned* smw, float c[4][4])
{
    const int t    = threadIdx.x;
    const int w    = t >> 5;
    const int lane = t & 31;
    const int g    = lane >> 2;
    const int tig  = lane & 3;
    const int wr   = w & 3, wc = w >> 2;
    const unsigned sbase = smem_u32(smw);

    const int lr = t >> 2, lp = t & 3;
    const unsigned* asrc = Ap + (size_t)(m0 + lr) * 256 + (lp < 2 ? lp * 8 : 128 + (lp - 2) * 8);
    const unsigned* bsrc = Bp + (size_t)(n0 + lr) * 256 + (lp < 2 ? lp * 8 : 128 + (lp - 2) * 8);
    const unsigned adst = sbase + (lr * 48 + lp * 8) * 4;
    const unsigned bdst = sbase + (GB_OFF + lr * 48 + lp * 8) * 4;

    #pragma unroll
    for (int ng = 0; ng < 4; ng++)
        #pragma unroll
        for (int i = 0; i < 4; i++) c[ng][i] = 0.0f;

    cpa16(adst, asrc); cpa16(adst + 16, asrc + 4);
    cpa16(bdst, bsrc); cpa16(bdst + 16, bsrc + 4);
    CP_COMMIT();

    #pragma unroll 1
    for (int ck = 0; ck < 8; ck++) {
        if (ck < 7) {
            const unsigned off = (unsigned)(((ck + 1) % 3) * GSTAGE_W * 4);
            const int so = (ck + 1) * 16;
            cpa16(adst + off, asrc + so); cpa16(adst + off + 16, asrc + so + 4);
            cpa16(bdst + off, bsrc + so); cpa16(bdst + off + 16, bsrc + so + 4);
            CP_COMMIT();
            CP_WAIT1();
        } else {
            CP_WAIT0();
        }
        __syncthreads();

        const unsigned* As = smw + (ck % 3) * GSTAGE_W;
        const unsigned* Bs = As + GB_OFF;

        const int r0 = wr * 16 + g;
        uint4 A0h = *(const uint4*)(As + r0 * 48 + 4 * tig);
        uint4 A8h = *(const uint4*)(As + (r0 + 8) * 48 + 4 * tig);
        uint4 A0l = *(const uint4*)(As + r0 * 48 + 16 + 4 * tig);
        uint4 A8l = *(const uint4*)(As + (r0 + 8) * 48 + 16 + 4 * tig);
        unsigned aH[8] = {A0h.x, A8h.x, A0h.y, A8h.y, A0h.z, A8h.z, A0h.w, A8h.w};
        unsigned aL[8] = {A0l.x, A8l.x, A0l.y, A8l.y, A0l.z, A8l.z, A0l.w, A8l.w};

        #pragma unroll
        for (int ng = 0; ng < 4; ng++) {
            const unsigned* br = Bs + (wc * 32 + 8 * ng + g) * 48;
            uint4 BH = *(const uint4*)(br + 4 * tig);
            uint4 BL = *(const uint4*)(br + 16 + 4 * tig);
            mma16816(c[ng], &aH[0], BH.x, BH.y);
            mma16816(c[ng], &aH[4], BH.z, BH.w);
            mma16816(c[ng], &aL[0], BH.x, BH.y);
            mma16816(c[ng], &aL[4], BH.z, BH.w);
            mma16816(c[ng], &aH[0], BL.x, BL.y);
            mma16816(c[ng], &aH[4], BL.z, BL.w);
        }
        __syncthreads();
    }
}

// ---------------------------------------------------------------------------
// QKV projection (mma). grid (4, 64, 3): n0 = 64x, m0 = 64y, z = matrix.
// ---------------------------------------------------------------------------
__global__ __launch_bounds__(256, 2) void qkv_mma_kernel(
    const float* __restrict__ bq, const float* __restrict__ bk, const float* __restrict__ bv)
{
    extern __shared__ __align__(16) unsigned smw[];
    const int z  = blockIdx.z;
    const int n0 = blockIdx.x * 64;
    const int m0 = blockIdx.y * 64;
    const int t    = threadIdx.x;
    const int w    = t >> 5;
    const int lane = t & 31;
    const int g    = lane >> 2;
    const int tig  = lane & 3;
    const int wr   = w & 3, wc = w >> 2;

    const unsigned* Ap = g_xp + (size_t)z * 4096 * 256;
    const unsigned* Bp = g_wp + (size_t)z * 65536;
    const float* bias = (z == 0) ? bq : (z == 1) ? bk : bv;

    float c[4][4];
    mma_gemm_core(Ap, Bp, m0, n0, smw, c);

    const int mrow = m0 + wr * 16 + g;

    if (z == 0) {
        #pragma unroll
        for (int ng = 0; ng < 4; ng++) {
            int n = n0 + wc * 32 + 8 * ng + 2 * tig;
            float b0 = bias[n], b1 = bias[n + 1];
            int h = n >> 5, d = n & 31;
            int l0 = mrow >> 1, bb0 = mrow & 1;
            int l1 = (mrow + 8) >> 1, bb1 = (mrow + 8) & 1;
            *(float2*)&g_q[(((size_t)(bb0 * 8 + h) * 2048 + l0) * 32) + d] =
                make_float2(c[ng][0] + b0, c[ng][1] + b1);
            *(float2*)&g_q[(((size_t)(bb1 * 8 + h) * 2048 + l1) * 32) + d] =
                make_float2(c[ng][2] + b0, c[ng][3] + b1);
        }
    } else if (z == 1) {
        #pragma unroll
        for (int ng = 0; ng < 4; ng++) {
            int n = n0 + wc * 32 + 8 * ng + 2 * tig;
            float b0 = bias[n], b1 = bias[n + 1];
            int h = n >> 5;
            int pos = p16i(((n & 31) >> 1));
            unsigned hw, lw;
            {
                int l = mrow >> 1, bb = mrow & 1;
                unsigned* row = g_k32 + ((size_t)(bb * 8 + h) * 2048 + l) * 32;
                split2(c[ng][0] + b0, c[ng][1] + b1, hw, lw);
                row[pos] = hw; row[16 + pos] = lw;
            }
            {
                int l = (mrow + 8) >> 1, bb = (mrow + 8) & 1;
                unsigned* row = g_k32 + ((size_t)(bb * 8 + h) * 2048 + l) * 32;
                split2(c[ng][2] + b0, c[ng][3] + b1, hw, lw);
                row[pos] = hw; row[16 + pos] = lw;
            }
        }
    } else {
        float* Cs = (float*)smw;   // [64][65]
        #pragma unroll
        for (int ng = 0; ng < 4; ng++) {
            int col = wc * 32 + 8 * ng + 2 * tig;
            int n = n0 + col;
            float b0 = bias[n], b1 = bias[n + 1];
            Cs[(wr * 16 + g) * 65 + col]     = c[ng][0] + b0;
            Cs[(wr * 16 + g) * 65 + col + 1] = c[ng][1] + b1;
            Cs[(wr * 16 + g + 8) * 65 + col]     = c[ng][2] + b0;
            Cs[(wr * 16 + g + 8) * 65 + col + 1] = c[ng][3] + b1;
        }
        __syncthreads();
        const int grp = t >> 3;
        const int lam = grp >> 1, bb = grp & 1;
        const int dl0 = (t & 7) * 8;
        const int kp  = (m0 >> 2) + lam;
        const int pos = (kp & ~31) + p32i(kp & 31);
        #pragma unroll
        for (int i = 0; i < 8; i++) {
            int dl = dl0 + i;
            int n = n0 + dl;
            int h = n >> 5, d = n & 31;
            float v0 = Cs[(4 * lam + bb) * 65 + dl];
            float v1 = Cs[(4 * lam + 2 + bb) * 65 + dl];
            unsigned hw, lw;
            split2(v0, v1, hw, lw);
            g_vh32[(size_t)(bb * 8 + h) * 32768 + d * 1024 + pos] = hw;
            g_vl32[(size_t)(bb * 8 + h) * 32768 + d * 1024 + pos] = lw;
        }
    }
}

// ---------------------------------------------------------------------------
// Output projection (mma). grid (4, 64).
// ---------------------------------------------------------------------------
__global__ __launch_bounds__(256, 2) void out_mma_kernel(
    const float* __restrict__ bias, float* __restrict__ out)
{
    extern __shared__ __align__(16) unsigned smw[];
    const int n0 = blockIdx.x * 64;
    const int m0 = blockIdx.y * 64;
    const int t    = threadIdx.x;
    const int w    = t >> 5;
    const int lane = t & 31;
    const int g    = lane >> 2;
    const int tig  = lane & 3;
    const int wr   = w & 3, wc = w >> 2;

    float c[4][4];
    mma_gemm_core(g_op, g_wp + 3 * 65536, m0, n0, smw, c);

    const int mrow = m0 + wr * 16 + g;
    #pragma unroll
    for (int ng = 0; ng < 4; ng++) {
        int n = n0 + wc * 32 + 8 * ng + 2 * tig;
        float b0 = bias[n], b1 = bias[n + 1];
        *(float2*)&out[(size_t)mrow * 256 + n] =
            make_float2(c[ng][0] + b0, c[ng][1] + b1);
        *(float2*)&out[(size_t)(mrow + 8) * 256 + n] =
            make_float2(c[ng][2] + b0, c[ng][3] + b1);
    }
}

// ---------------------------------------------------------------------------
// Flash attention. grid (16, 16), 256 threads, 2 CTAs/SM.
// SMEM stage: K 64x48 (32 data words permuted p16/half), Vh 32x48, Vl 32x48
// (p32 per segment). All fragment loads LDS.128, conflict-free.
// ---------------------------------------------------------------------------
#define AVH_OFF  3072
#define AVL_OFF  4608
#define ASTAGE_W 6144
#define ATTN_SMEM (3 * ASTAGE_W * 4)   // 73728 B

__global__ __launch_bounds__(256, 2) void attn_kernel()
{
    extern __shared__ __align__(16) unsigned smw[];
    const unsigned sbase = smem_u32(smw);

    const int t    = threadIdx.x;
    const int w    = t >> 5;
    const int lane = t & 31;
    const int g    = lane >> 2;
    const int tig  = lane & 3;

    const int bh = blockIdx.y;
    const int b  = bh >> 3;
    const int h  = bh & 7;
    const int q0 = blockIdx.x * 128;

    const float* Qg = g_q + (size_t)bh * L_SEQ * D_DIM;

    unsigned qah[8], qal[8];
    {
        const int r0 = q0 + w * 16 + g;
        const int t2 = tig * 2;
        #pragma unroll
        for (int half = 0; half < 2; half++) {
            int dbase = half * 16;
            float2 xa = *(const float2*)&Qg[(size_t)r0 * 32 + dbase + t2];
            float2 xb = *(const float2*)&Qg[(size_t)(r0 + 8) * 32 + dbase + t2];
            float2 xc = *(const float2*)&Qg[(size_t)r0 * 32 + dbase + t2 + 8];
            float2 xd = *(const float2*)&Qg[(size_t)(r0 + 8) * 32 + dbase + t2 + 8];
            split2(xa.x * SC2, xa.y * SC2, qah[half * 4 + 0], qal[half * 4 + 0]);
            split2(xb.x * SC2, xb.y * SC2, qah[half * 4 + 1], qal[half * 4 + 1]);
            split2(xc.x * SC2, xc.y * SC2, qah[half * 4 + 2], qal[half * 4 + 2]);
            split2(xd.x * SC2, xd.y * SC2, qah[half * 4 + 3], qal[half * 4 + 3]);
        }
    }

    const int kkey = t >> 2;
    const int kjw  = (t & 3) * 8;
    const int vd   = t >> 3;
    const int vjw  = (t & 7) * 4;
    const unsigned* ksrc0  = g_k32  + (size_t)bh * 65536 + kkey * 32 + kjw;
    const unsigned* vhsrc0 = g_vh32 + (size_t)bh * 32768 + vd * 1024 + vjw;
    const unsigned* vlsrc0 = g_vl32 + (size_t)bh * 32768 + vd * 1024 + vjw;
    const unsigned kdst0  = sbase + (kkey * 48 + kjw) * 4;
    const unsigned vhdst0 = sbase + (AVH_OFF + vd * 48 + vjw) * 4;
    const unsigned vldst0 = sbase + (AVL_OFF + vd * 48 + vjw) * 4;

    float o[4][4];
    #pragma unroll
    for (int m = 0; m < 4; m++)
        #pragma unroll
        for (int i = 0; i < 4; i++) o[m][i] = 0.0f;
    float lsum0 = 0.0f, lsum1 = 0.0f;

    {
        cpa16(kdst0,      ksrc0);
        cpa16(kdst0 + 16, ksrc0 + 4);
        cpa16(vhdst0, vhsrc0);
        cpa16(vldst0, vlsrc0);
        CP_COMMIT();
    }

    #pragma unroll 1
    for (int kt = 0; kt < 32; kt++) {
        const int s = kt % 3;
        if (kt < 31) {
            const unsigned off = (unsigned)(((kt + 1) % 3) * ASTAGE_W * 4);
            cpa16(kdst0 + off,      ksrc0 + (kt + 1) * 2048);
            cpa16(kdst0 + off + 16, ksrc0 + (kt + 1) * 2048 + 4);
            cpa16(vhdst0 + off, vhsrc0 + (kt + 1) * 32);
            cpa16(vldst0 + off, vlsrc0 + (kt + 1) * 32);
            CP_COMMIT();
            CP_WAIT1();
        } else {
            CP_WAIT0();
        }
        __syncthreads();

        const unsigned* Ksb = smw + s * ASTAGE_W;
        const unsigned* Vhb = Ksb + AVH_OFF;
        const unsigned* Vlb = Ksb + AVL_OFF;

        unsigned ph[4][4], pl[4][4];
        #pragma unroll
        for (int ng = 0; ng < 8; ng++) {
            const unsigned* krow = Ksb + (8 * ng + g) * 48;
            uint4 KH = *(const uint4*)(krow + 4 * tig);
            uint4 KL = *(const uint4*)(krow + 16 + 4 * tig);

            float s4[4] = {0.f, 0.f, 0.f, 0.f};
            mma16816(s4, &qah[0], KH.x, KH.y);
            mma16816(s4, &qah[4], KH.z, KH.w);
            mma16816(s4, &qal[0], KH.x, KH.y);
            mma16816(s4, &qal[4], KH.z, KH.w);
            mma16816(s4, &qah[0], KL.x, KL.y);
            mma16816(s4, &qah[4], KL.z, KL.w);

            float p0 = ex2(s4[0]), p1 = ex2(s4[1]);
            float p2 = ex2(s4[2]), p3 = ex2(s4[3]);
            lsum0 += p0 + p1;
            lsum1 += p2 + p3;

            int si = ng >> 1, hf = (ng & 1) * 2;
            split2(p0, p1, ph[si][hf],     pl[si][hf]);
            split2(p2, p3, ph[si][hf + 1], pl[si][hf + 1]);
        }

        #pragma unroll
        for (int m = 0; m < 4; m++) {
            const unsigned* vhrow = Vhb + (8 * m + g) * 48;
            const unsigned* vlrow = Vlb + (8 * m + g) * 48;
            unsigned vh0[4], vh1[4], vl0[4], vl1[4];
            *(uint4*)vh0 = *(const uint4*)(vhrow + 4 * tig);
            *(uint4*)vh1 = *(const uint4*)(vhrow + 16 + 4 * tig);
            *(uint4*)vl0 = *(const uint4*)(vlrow + 4 * tig);
            *(uint4*)vl1 = *(const uint4*)(vlrow + 16 + 4 * tig);
            #pragma unroll
            for (int sk = 0; sk < 4; sk++) {
                mma16816(o[m], ph[sk], vh0[sk], vh1[sk]);
                mma16816(o[m], pl[sk], vh0[sk], vh1[sk]);
                mma16816(o[m], ph[sk], vl0[sk], vl1[sk]);
            }
        }
    }

    lsum0 += __shfl_xor_sync(0xffffffffu, lsum0, 1);
    lsum0 += __shfl_xor_sync(0xffffffffu, lsum0, 2);
    lsum1 += __shfl_xor_sync(0xffffffffu, lsum1, 1);
    lsum1 += __shfl_xor_sync(0xffffffffu, lsum1, 2);
    const float inv0 = 1.0f / lsum0;
    const float inv1 = 1.0f / lsum1;

    // Epilogue: packed + permuted A-operand for out_proj.
    // word = h*16 + p16(4m+tig) = h*16 + 4*tig + m
    const int l0 = q0 + w * 16 + g;
    const int row0 = l0 * 2 + b;
    const int row1 = (l0 + 8) * 2 + b;
    #pragma unroll
    for (int m = 0; m < 4; m++) {
        int word = h * 16 + 4 * tig + m;
        unsigned hw, lw;
        split2(o[m][0] * inv0, o[m][1] * inv0, hw, lw);
        g_op[(size_t)row0 * 256 + word]       = hw;
        g_op[(size_t)row0 * 256 + 128 + word] = lw;
        split2(o[m][2] * inv1, o[m][3] * inv1, hw, lw);
        g_op[(size_t)row1 * 256 + word]       = hw;
        g_op[(size_t)row1 * 256 + 128 + word] = lw;
    }
}

// ---------------------------------------------------------------------------
extern "C" void kernel_launch(void* const* d_in, const int* in_sizes, int n_in,
                              void* d_out, int out_size)
{
    (void)in_sizes; (void)n_in; (void)out_size;
    const float* query = (const float*)d_in[0];
    const float* key_  = (const float*)d_in[1];
    const float* value = (const float*)d_in[2];
    const float* Wq    = (const float*)d_in[3];
    const float* bq    = (const float*)d_in[4];
    const float* Wk    = (const float*)d_in[5];
    const float* bk    = (const float*)d_in[6];
    const float* Wv    = (const float*)d_in[7];
    const float* bv    = (const float*)d_in[8];
    const float* Wp    = (const float*)d_in[9];
    const float* bp    = (const float*)d_in[10];
    float* out = (float*)d_out;

    cudaFuncSetAttribute(attn_kernel,
                         cudaFuncAttributeMaxDynamicSharedMemorySize, ATTN_SMEM);
    cudaFuncSetAttribute(qkv_mma_kernel,
                         cudaFuncAttributeMaxDynamicSharedMemorySize, GEMM_SMEM);
    cudaFuncSetAttribute(out_mma_kernel,
                         cudaFuncAttributeMaxDynamicSharedMemorySize, GEMM_SMEM);

    prep_kernel<<<64, 256>>>(query, key_, value, Wq, Wk, Wv, Wp);
    qkv_mma_kernel<<<dim3(4, 64, 3), 256, GEMM_SMEM>>>(bq, bk, bv);
    attn_kernel<<<dim3(L_SEQ / 128, B_SZ * H_CNT), 256, ATTN_SMEM>>>();
    out_mma_kernel<<<dim3(4, 64), 256, GEMM_SMEM>>>(bp, out);
}